// round 1
// baseline (speedup 1.0000x reference)
#include <cuda_runtime.h>

// Problem constants
#define BB 4
#define SS 2048
#define EE 1024
#define HH 16
#define DD 64
#define MTOK (BB * SS)     // 8192 tokens
#define NQKV (3 * EE)      // 3072
#define SCALE 0.125f       // 1/sqrt(64)

// ---------------------------------------------------------------------------
// Scratch (device globals — no allocation allowed in kernel_launch)
// ---------------------------------------------------------------------------
__device__ float g_q[MTOK * EE];               // Q as [m][h*64+d]   (32 MB)
__device__ float g_k[BB * HH][SS][DD];          // K as [bh][s][d]    (33.5 MB)
__device__ float g_v[BB * HH][SS][DD];          // V as [bh][s][d]    (33.5 MB)
__device__ float g_m[BB][HH][DD][DD];           // M[b,h] = scale*K^T V (1 MB)
__device__ float g_p[BB][EE][EE];               // P[b] = blockdiag(M) @ Wo^T (16 MB)

// ---------------------------------------------------------------------------
// Kernel A: QKV projection.  C = X @ Wqkv^T  (8192 x 3072, K=1024)
// X row-major [m][k], Wqkv row-major [n][k] -> both K-contiguous.
// Epilogue scatters into g_q / g_k / g_v per the (h, 3D) interleaved layout:
//   column n: h = n/192, j = n%192; j<64 -> Q, j<128 -> K, else -> V.
// Tiling: 128x128 block, BK=16, 256 threads, 8x8 per thread.
// ---------------------------------------------------------------------------
__global__ __launch_bounds__(256) void qkv_gemm(const float* __restrict__ x,
                                                const float* __restrict__ w) {
    __shared__ float As[16][128];
    __shared__ float Bs[16][128];

    const int bn  = blockIdx.x * 128;
    const int bm  = blockIdx.y * 128;
    const int tid = threadIdx.x;
    const int tx  = tid & 15;        // -> n micro-tile
    const int ty  = tid >> 4;        // -> m micro-tile

    float acc[8][8];
#pragma unroll
    for (int i = 0; i < 8; ++i)
#pragma unroll
        for (int j = 0; j < 8; ++j) acc[i][j] = 0.0f;

    for (int k0 = 0; k0 < EE; k0 += 16) {
        // Load A tile (128 x 16) and B tile (128 x 16), both transposed into smem.
        // 512 float4 per tile, 2 per thread.
#pragma unroll
        for (int it = 0; it < 2; ++it) {
            const int fid = tid + it * 256;     // 0..511
            const int row = fid >> 2;           // 0..127
            const int c4  = (fid & 3) * 4;      // 0,4,8,12
            float4 va = *(const float4*)&x[(size_t)(bm + row) * EE + k0 + c4];
            As[c4 + 0][row] = va.x; As[c4 + 1][row] = va.y;
            As[c4 + 2][row] = va.z; As[c4 + 3][row] = va.w;
            float4 vb = *(const float4*)&w[(size_t)(bn + row) * EE + k0 + c4];
            Bs[c4 + 0][row] = vb.x; Bs[c4 + 1][row] = vb.y;
            Bs[c4 + 2][row] = vb.z; Bs[c4 + 3][row] = vb.w;
        }
        __syncthreads();

#pragma unroll
        for (int k = 0; k < 16; ++k) {
            float a[8], b[8];
            float4 a0 = *(const float4*)&As[k][ty * 8];
            float4 a1 = *(const float4*)&As[k][ty * 8 + 4];
            float4 b0 = *(const float4*)&Bs[k][tx * 8];
            float4 b1 = *(const float4*)&Bs[k][tx * 8 + 4];
            a[0]=a0.x; a[1]=a0.y; a[2]=a0.z; a[3]=a0.w;
            a[4]=a1.x; a[5]=a1.y; a[6]=a1.z; a[7]=a1.w;
            b[0]=b0.x; b[1]=b0.y; b[2]=b0.z; b[3]=b0.w;
            b[4]=b1.x; b[5]=b1.y; b[6]=b1.z; b[7]=b1.w;
#pragma unroll
            for (int i = 0; i < 8; ++i)
#pragma unroll
                for (int j = 0; j < 8; ++j) acc[i][j] += a[i] * b[j];
        }
        __syncthreads();
    }

    // Scatter epilogue
#pragma unroll
    for (int i = 0; i < 8; ++i) {
        const int m = bm + ty * 8 + i;
        const int bidx = m >> 11;          // / 2048
        const int s    = m & 2047;
#pragma unroll
        for (int j = 0; j < 8; ++j) {
            const int n  = bn + tx * 8 + j;
            const int h  = n / 192;
            const int jj = n - h * 192;
            const float val = acc[i][j];
            if (jj < 64) {
                g_q[(size_t)m * EE + h * 64 + jj] = val;
            } else if (jj < 128) {
                g_k[bidx * HH + h][s][jj - 64] = val;
            } else {
                g_v[bidx * HH + h][s][jj - 128] = val;
            }
        }
    }
}

// ---------------------------------------------------------------------------
// Kernel B: M[b,h] = SCALE * K_h^T @ V_h   (64x64, reduce over S=2048)
// One block per (b,h). 256 threads, each computes a 4x4 patch of M.
// ---------------------------------------------------------------------------
__global__ __launch_bounds__(256) void kv_reduce() {
    const int bh  = blockIdx.x;             // 0..63
    const int tid = threadIdx.x;
    const int tx  = tid & 15;               // -> d2 (V dim)
    const int ty  = tid >> 4;               // -> d1 (K dim)

    __shared__ float Ks[32][64];
    __shared__ float Vs[32][64];

    float acc[4][4];
#pragma unroll
    for (int i = 0; i < 4; ++i)
#pragma unroll
        for (int j = 0; j < 4; ++j) acc[i][j] = 0.0f;

    for (int s0 = 0; s0 < SS; s0 += 32) {
        // 32x64 floats each = 512 float4; 2 per thread
#pragma unroll
        for (int it = 0; it < 2; ++it) {
            const int fid = tid + it * 256;
            const int row = fid >> 4;            // 64 floats = 16 float4/row
            const int c4  = (fid & 15) * 4;
            *(float4*)&Ks[row][c4] = *(const float4*)&g_k[bh][s0 + row][c4];
            *(float4*)&Vs[row][c4] = *(const float4*)&g_v[bh][s0 + row][c4];
        }
        __syncthreads();

#pragma unroll 8
        for (int s = 0; s < 32; ++s) {
            float a[4], b[4];
#pragma unroll
            for (int i = 0; i < 4; ++i) a[i] = Ks[s][ty * 4 + i];
#pragma unroll
            for (int j = 0; j < 4; ++j) b[j] = Vs[s][tx * 4 + j];
#pragma unroll
            for (int i = 0; i < 4; ++i)
#pragma unroll
                for (int j = 0; j < 4; ++j) acc[i][j] += a[i] * b[j];
        }
        __syncthreads();
    }

    const int b = bh / HH, h = bh % HH;
#pragma unroll
    for (int i = 0; i < 4; ++i)
#pragma unroll
        for (int j = 0; j < 4; ++j)
            g_m[b][h][ty * 4 + i][tx * 4 + j] = SCALE * acc[i][j];
}

// ---------------------------------------------------------------------------
// Kernel C: P[b][r][c] = sum_{d'} M[b][r/64][r%64][d'] * w_o[c][(r/64)*64 + d']
// 64x64 output tile per block; grid (E/64, H, B). K = 64.
// ---------------------------------------------------------------------------
__global__ __launch_bounds__(256) void make_p(const float* __restrict__ w_o) {
    const int b  = blockIdx.z;
    const int h  = blockIdx.y;
    const int c0 = blockIdx.x * 64;
    const int tid = threadIdx.x;
    const int tx  = tid & 15;        // -> c
    const int ty  = tid >> 4;        // -> r (within head block)

    __shared__ float Ms[64][64];     // Ms[d_r][d']
    __shared__ float Wos[64][64];    // Wos[c-c0][d']

    // 4096 floats each = 1024 float4; 4 per thread
#pragma unroll
    for (int it = 0; it < 4; ++it) {
        const int fid = tid + it * 256;
        const int row = fid >> 4;
        const int c4  = (fid & 15) * 4;
        *(float4*)&Ms[row][c4]  = *(const float4*)&g_m[b][h][row][c4];
        *(float4*)&Wos[row][c4] = *(const float4*)&w_o[(size_t)(c0 + row) * EE + h * 64 + c4];
    }
    __syncthreads();

    float acc[4][4];
#pragma unroll
    for (int i = 0; i < 4; ++i)
#pragma unroll
        for (int j = 0; j < 4; ++j) acc[i][j] = 0.0f;

#pragma unroll 8
    for (int d = 0; d < 64; ++d) {
        float a[4], bb[4];
#pragma unroll
        for (int i = 0; i < 4; ++i) a[i] = Ms[ty * 4 + i][d];
#pragma unroll
        for (int j = 0; j < 4; ++j) bb[j] = Wos[tx * 4 + j][d];
#pragma unroll
        for (int i = 0; i < 4; ++i)
#pragma unroll
            for (int j = 0; j < 4; ++j) acc[i][j] += a[i] * bb[j];
    }

#pragma unroll
    for (int i = 0; i < 4; ++i)
#pragma unroll
        for (int j = 0; j < 4; ++j)
            g_p[b][h * 64 + ty * 4 + i][c0 + tx * 4 + j] = acc[i][j];
}

// ---------------------------------------------------------------------------
// Kernel D: out = Q_flat @ P[b]   (8192 x 1024, K = 1024)
// Q row-major [m][k], P row-major [k][n] (not transposed).
// Same 128x128/BK=16 tiling as kernel A.
// ---------------------------------------------------------------------------
__global__ __launch_bounds__(256) void out_gemm(float* __restrict__ out) {
    __shared__ float As[16][128];
    __shared__ float Bs[16][128];

    const int bn  = blockIdx.x * 128;
    const int bm  = blockIdx.y * 128;
    const int b   = bm >> 11;               // batch (128 | 2048)
    const int tid = threadIdx.x;
    const int tx  = tid & 15;
    const int ty  = tid >> 4;

    float acc[8][8];
#pragma unroll
    for (int i = 0; i < 8; ++i)
#pragma unroll
        for (int j = 0; j < 8; ++j) acc[i][j] = 0.0f;

    for (int k0 = 0; k0 < EE; k0 += 16) {
#pragma unroll
        for (int it = 0; it < 2; ++it) {
            const int fid = tid + it * 256;
            // A tile: 128 rows x 16 cols, transposed store
            {
                const int row = fid >> 2;
                const int c4  = (fid & 3) * 4;
                float4 va = *(const float4*)&g_q[(size_t)(bm + row) * EE + k0 + c4];
                As[c4 + 0][row] = va.x; As[c4 + 1][row] = va.y;
                As[c4 + 2][row] = va.z; As[c4 + 3][row] = va.w;
            }
            // B tile: 16 rows(k) x 128 cols(n), direct store
            {
                const int krow = fid >> 5;           // 128 floats = 32 float4/row
                const int c4   = (fid & 31) * 4;
                *(float4*)&Bs[krow][c4] = *(const float4*)&g_p[b][k0 + krow][bn + c4];
            }
        }
        __syncthreads();

#pragma unroll
        for (int k = 0; k < 16; ++k) {
            float a[8], bb[8];
            float4 a0 = *(const float4*)&As[k][ty * 8];
            float4 a1 = *(const float4*)&As[k][ty * 8 + 4];
            float4 b0 = *(const float4*)&Bs[k][tx * 8];
            float4 b1 = *(const float4*)&Bs[k][tx * 8 + 4];
            a[0]=a0.x; a[1]=a0.y; a[2]=a0.z; a[3]=a0.w;
            a[4]=a1.x; a[5]=a1.y; a[6]=a1.z; a[7]=a1.w;
            bb[0]=b0.x; bb[1]=b0.y; bb[2]=b0.z; bb[3]=b0.w;
            bb[4]=b1.x; bb[5]=b1.y; bb[6]=b1.z; bb[7]=b1.w;
#pragma unroll
            for (int i = 0; i < 8; ++i)
#pragma unroll
                for (int j = 0; j < 8; ++j) acc[i][j] += a[i] * bb[j];
        }
        __syncthreads();
    }

#pragma unroll
    for (int i = 0; i < 8; ++i) {
        const int m = bm + ty * 8 + i;
#pragma unroll
        for (int j = 0; j < 8; j += 4) {
            float4 v;
            v.x = acc[i][j + 0];
            v.y = acc[i][j + 1];
            v.z = acc[i][j + 2];
            v.w = acc[i][j + 3];
            *(float4*)&out[(size_t)m * EE + bn + tx * 8 + j] = v;
        }
    }
}

// ---------------------------------------------------------------------------
// Launch
// ---------------------------------------------------------------------------
extern "C" void kernel_launch(void* const* d_in, const int* in_sizes, int n_in,
                              void* d_out, int out_size) {
    const float* x     = (const float*)d_in[0];
    const float* w_qkv = (const float*)d_in[1];
    const float* w_o   = (const float*)d_in[2];
    float* out = (float*)d_out;

    qkv_gemm<<<dim3(NQKV / 128, MTOK / 128), 256>>>(x, w_qkv);
    kv_reduce<<<BB * HH, 256>>>();
    make_p<<<dim3(EE / 64, HH, BB), 256>>>(w_o);
    out_gemm<<<dim3(EE / 128, MTOK / 128), 256>>>(out);
}

// round 3
// speedup vs baseline: 1.4259x; 1.4259x over previous
#include <cuda_runtime.h>
#include <cstdint>
#include <cstddef>

// Problem constants
#define BB 4
#define SS 2048
#define EE 1024
#define HH 16
#define DD 64
#define MTOK (BB * SS)     // 8192
#define NQKV (3 * EE)      // 3072
#define SCALE 0.125f
#define NSLICE 8

#define BK 32
#define PAD_ROW 36                     // floats per smem row (conflict-free frag LDS)
#define ABYTES (128 * PAD_ROW * 4)     // 18432 per operand tile
#define STAGE (2 * ABYTES)             // A + B per stage
#define SMEM_BYTES (2 * STAGE)         // double buffered = 73728

// ---------------------------------------------------------------------------
// Scratch
// ---------------------------------------------------------------------------
__device__ float g_q[MTOK * EE];
__device__ float g_k[BB * HH][SS][DD];
__device__ float g_v[BB * HH][SS][DD];
__device__ float g_mpart[NSLICE][BB * HH][DD][DD];
__device__ float g_m[BB][HH][DD][DD];
__device__ float g_pt[BB][EE][EE];     // P^T [b][n][k]

// ---------------------------------------------------------------------------
// Helpers
// ---------------------------------------------------------------------------
__device__ __forceinline__ uint32_t smem_u32(const void* p) {
    uint32_t a;
    asm("{ .reg .u64 t; cvta.to.shared.u64 t, %1; cvt.u32.u64 %0, t; }" : "=r"(a) : "l"(p));
    return a;
}
__device__ __forceinline__ void cpasync16(uint32_t s, const void* g) {
    asm volatile("cp.async.cg.shared.global [%0], [%1], 16;" :: "r"(s), "l"(g));
}
#define CP_COMMIT() asm volatile("cp.async.commit_group;" ::: "memory")
#define CP_WAIT0()  asm volatile("cp.async.wait_group 0;" ::: "memory")

__device__ __forceinline__ void split1(float v, uint32_t& h, uint32_t& l) {
    asm("cvt.rna.tf32.f32 %0, %1;" : "=r"(h) : "f"(v));
    l = __float_as_uint(v - __uint_as_float(h));
}
__device__ __forceinline__ void mma8(float* c, const uint32_t* a, const uint32_t* b) {
    asm volatile(
        "mma.sync.aligned.m16n8k8.row.col.f32.tf32.tf32.f32 "
        "{%0,%1,%2,%3}, {%4,%5,%6,%7}, {%8,%9}, {%0,%1,%2,%3};"
        : "+f"(c[0]), "+f"(c[1]), "+f"(c[2]), "+f"(c[3])
        : "r"(a[0]), "r"(a[1]), "r"(a[2]), "r"(a[3]), "r"(b[0]), "r"(b[1]));
}

// ---------------------------------------------------------------------------
// Tensor-core GEMM (tf32 x3 split).  C[128x128] tiles, BK=32, 256 threads.
// A: [m][k] row-major K-contig.  B: [n][k] row-major K-contig ("col" operand).
// MODE 0: qkv (scatter epilogue into g_q/g_k/g_v)
// MODE 1: out (direct epilogue)
// ---------------------------------------------------------------------------
template <int MODE>
__global__ __launch_bounds__(256, 1) void gemm_mma(const float* __restrict__ A,
                                                   const float* __restrict__ Bmat,
                                                   float* __restrict__ Out) {
    extern __shared__ float sm[];
    const int tid = threadIdx.x;
    const int wid = tid >> 5, lane = tid & 31;
    const int g = lane >> 2, tg = lane & 3;
    const int warp_m = wid & 3;        // 4 x 32 rows
    const int warp_n = wid >> 2;       // 2 x 64 cols
    const int bn = blockIdx.x * 128;
    const int bm = blockIdx.y * 128;

    const float* Ap;
    const float* Bp;
    if (MODE == 0) {
        Ap = A + (size_t)bm * EE;
        Bp = Bmat + (size_t)bn * EE;
    } else {
        const int batch = bm >> 11;
        Ap = &g_q[0] + (size_t)bm * EE;
        Bp = &g_pt[0][0][0] + ((size_t)batch * EE + bn) * EE;
    }

    const uint32_t sbase = smem_u32(sm);

    float acc[2][8][4];
#pragma unroll
    for (int mt = 0; mt < 2; ++mt)
#pragma unroll
        for (int nt = 0; nt < 8; ++nt)
#pragma unroll
            for (int i = 0; i < 4; ++i) acc[mt][nt][i] = 0.0f;

    // stage loader: 128x32 fp32 tile for A and B via cp.async (16B)
    auto load_stage = [&](int s, int k0) {
        const uint32_t base = sbase + s * STAGE;
#pragma unroll
        for (int i = 0; i < 4; ++i) {
            const int fid = tid + i * 256;
            const int row = fid >> 3;
            const int c4 = (fid & 7) * 4;            // float offset
            const uint32_t so = row * (PAD_ROW * 4) + c4 * 4;
            cpasync16(base + so, Ap + (size_t)row * EE + k0 + c4);
            cpasync16(base + ABYTES + so, Bp + (size_t)row * EE + k0 + c4);
        }
        CP_COMMIT();
    };

    load_stage(0, 0);

    const int NK = EE / BK;            // 32
    for (int kc = 0; kc < NK; ++kc) {
        const int b = kc & 1;
        CP_WAIT0();
        __syncthreads();
        if (kc + 1 < NK) load_stage((kc + 1) & 1, (kc + 1) * BK);

        const float* As = sm + b * (STAGE / 4);
        const float* Bs = As + 128 * PAD_ROW;

#pragma unroll
        for (int ks = 0; ks < 4; ++ks) {
            const int kk = ks * 8 + tg;
            uint32_t ahi[2][4], alo[2][4];
#pragma unroll
            for (int mt = 0; mt < 2; ++mt) {
                const int mb = warp_m * 32 + mt * 16;
                split1(As[(mb + g) * PAD_ROW + kk],         ahi[mt][0], alo[mt][0]);
                split1(As[(mb + g + 8) * PAD_ROW + kk],     ahi[mt][1], alo[mt][1]);
                split1(As[(mb + g) * PAD_ROW + kk + 4],     ahi[mt][2], alo[mt][2]);
                split1(As[(mb + g + 8) * PAD_ROW + kk + 4], ahi[mt][3], alo[mt][3]);
            }
            uint32_t bhi[8][2], blo[8][2];
#pragma unroll
            for (int nt = 0; nt < 8; ++nt) {
                const int nb = warp_n * 64 + nt * 8;
                split1(Bs[(nb + g) * PAD_ROW + kk],     bhi[nt][0], blo[nt][0]);
                split1(Bs[(nb + g) * PAD_ROW + kk + 4], bhi[nt][1], blo[nt][1]);
            }
#pragma unroll
            for (int mt = 0; mt < 2; ++mt)
#pragma unroll
                for (int nt = 0; nt < 8; ++nt) mma8(acc[mt][nt], ahi[mt], bhi[nt]);
#pragma unroll
            for (int mt = 0; mt < 2; ++mt)
#pragma unroll
                for (int nt = 0; nt < 8; ++nt) mma8(acc[mt][nt], alo[mt], bhi[nt]);
#pragma unroll
            for (int mt = 0; mt < 2; ++mt)
#pragma unroll
                for (int nt = 0; nt < 8; ++nt) mma8(acc[mt][nt], ahi[mt], blo[nt]);
        }
        __syncthreads();
    }

    // Epilogue: direct register -> gmem float2 stores.
#pragma unroll
    for (int mt = 0; mt < 2; ++mt) {
#pragma unroll
        for (int nt = 0; nt < 8; ++nt) {
            const int col = bn + warp_n * 64 + nt * 8 + 2 * tg;
#pragma unroll
            for (int half = 0; half < 2; ++half) {
                const int row = bm + warp_m * 32 + mt * 16 + g + half * 8;
                const float v0 = acc[mt][nt][half * 2 + 0];
                const float v1 = acc[mt][nt][half * 2 + 1];
                if (MODE == 1) {
                    *(float2*)&Out[(size_t)row * EE + col] = make_float2(v0, v1);
                } else {
                    const int h = col / 192;
                    const int jj = col - h * 192;
                    const int bidx = row >> 11;
                    const int s = row & 2047;
                    if (jj < 64)
                        *(float2*)&g_q[(size_t)row * EE + h * 64 + jj] = make_float2(v0, v1);
                    else if (jj < 128)
                        *(float2*)&g_k[bidx * HH + h][s][jj - 64] = make_float2(v0, v1);
                    else
                        *(float2*)&g_v[bidx * HH + h][s][jj - 128] = make_float2(v0, v1);
                }
            }
        }
    }
}

// ---------------------------------------------------------------------------
// kv_reduce partials: grid (64, NSLICE)
// ---------------------------------------------------------------------------
__global__ __launch_bounds__(256) void kv_reduce() {
    const int bh = blockIdx.x;
    const int sl = blockIdx.y;
    const int tid = threadIdx.x;
    const int tx = tid & 15;
    const int ty = tid >> 4;

    __shared__ float Ks[32][64];
    __shared__ float Vs[32][64];

    float acc[4][4];
#pragma unroll
    for (int i = 0; i < 4; ++i)
#pragma unroll
        for (int j = 0; j < 4; ++j) acc[i][j] = 0.0f;

    const int s_beg = sl * (SS / NSLICE);
    for (int s0 = s_beg; s0 < s_beg + SS / NSLICE; s0 += 32) {
#pragma unroll
        for (int it = 0; it < 2; ++it) {
            const int fid = tid + it * 256;
            const int row = fid >> 4;
            const int c4 = (fid & 15) * 4;
            *(float4*)&Ks[row][c4] = *(const float4*)&g_k[bh][s0 + row][c4];
            *(float4*)&Vs[row][c4] = *(const float4*)&g_v[bh][s0 + row][c4];
        }
        __syncthreads();
#pragma unroll 8
        for (int s = 0; s < 32; ++s) {
            float a[4], b[4];
#pragma unroll
            for (int i = 0; i < 4; ++i) a[i] = Ks[s][ty * 4 + i];
#pragma unroll
            for (int j = 0; j < 4; ++j) b[j] = Vs[s][tx * 4 + j];
#pragma unroll
            for (int i = 0; i < 4; ++i)
#pragma unroll
                for (int j = 0; j < 4; ++j) acc[i][j] += a[i] * b[j];
        }
        __syncthreads();
    }
#pragma unroll
    for (int i = 0; i < 4; ++i)
#pragma unroll
        for (int j = 0; j < 4; ++j)
            g_mpart[sl][bh][ty * 4 + i][tx * 4 + j] = acc[i][j];
}

__global__ __launch_bounds__(256) void merge_m() {
    const int bh = blockIdx.x;
    const int b = bh / HH, h = bh % HH;
    for (int e = threadIdx.x; e < DD * DD; e += 256) {
        float s = 0.0f;
#pragma unroll
        for (int p = 0; p < NSLICE; ++p) s += g_mpart[p][bh][e >> 6][e & 63];
        g_m[b][h][e >> 6][e & 63] = SCALE * s;
    }
}

// ---------------------------------------------------------------------------
// make_p: g_pt[b][c][r] = sum_d M[b][r/64][r%64][d] * w_o[c][(r/64)*64+d]
// ---------------------------------------------------------------------------
__global__ __launch_bounds__(256) void make_p(const float* __restrict__ w_o) {
    const int b = blockIdx.z;
    const int h = blockIdx.y;
    const int c0 = blockIdx.x * 64;
    const int tid = threadIdx.x;
    const int tx = tid & 15;   // rl
    const int ty = tid >> 4;   // c

    __shared__ float Ms[64][64];
    __shared__ float Wos[64][64];

#pragma unroll
    for (int it = 0; it < 4; ++it) {
        const int fid = tid + it * 256;
        const int row = fid >> 4;
        const int c4 = (fid & 15) * 4;
        *(float4*)&Ms[row][c4] = *(const float4*)&g_m[b][h][row][c4];
        *(float4*)&Wos[row][c4] = *(const float4*)&w_o[(size_t)(c0 + row) * EE + h * 64 + c4];
    }
    __syncthreads();

    float acc[4][4];
#pragma unroll
    for (int i = 0; i < 4; ++i)
#pragma unroll
        for (int j = 0; j < 4; ++j) acc[i][j] = 0.0f;

#pragma unroll 8
    for (int d = 0; d < 64; ++d) {
        float a[4], bb[4];
#pragma unroll
        for (int i = 0; i < 4; ++i) a[i] = Wos[ty * 4 + i][d];
#pragma unroll
        for (int j = 0; j < 4; ++j) bb[j] = Ms[tx * 4 + j][d];
#pragma unroll
        for (int i = 0; i < 4; ++i)
#pragma unroll
            for (int j = 0; j < 4; ++j) acc[i][j] += a[i] * bb[j];
    }

#pragma unroll
    for (int i = 0; i < 4; ++i) {
        float4 v;
        v.x = acc[i][0]; v.y = acc[i][1]; v.z = acc[i][2]; v.w = acc[i][3];
        *(float4*)&g_pt[b][c0 + ty * 4 + i][h * 64 + tx * 4] = v;
    }
}

// ---------------------------------------------------------------------------
// Launch
// ---------------------------------------------------------------------------
extern "C" void kernel_launch(void* const* d_in, const int* in_sizes, int n_in,
                              void* d_out, int out_size) {
    const float* x = (const float*)d_in[0];
    const float* w_qkv = (const float*)d_in[1];
    const float* w_o = (const float*)d_in[2];
    float* out = (float*)d_out;

    cudaFuncSetAttribute(gemm_mma<0>, cudaFuncAttributeMaxDynamicSharedMemorySize, SMEM_BYTES);
    cudaFuncSetAttribute(gemm_mma<1>, cudaFuncAttributeMaxDynamicSharedMemorySize, SMEM_BYTES);

    gemm_mma<0><<<dim3(NQKV / 128, MTOK / 128), 256, SMEM_BYTES>>>(x, w_qkv, nullptr);
    kv_reduce<<<dim3(BB * HH, NSLICE), 256>>>();
    merge_m<<<BB * HH, 256>>>();
    make_p<<<dim3(EE / 64, HH, BB), 256>>>(w_o);
    gemm_mma<1><<<dim3(EE / 128, MTOK / 128), 256, SMEM_BYTES>>>(nullptr, nullptr, out);
}

// round 5
// speedup vs baseline: 2.6077x; 1.8288x over previous
#include <cuda_runtime.h>
#include <cstdint>
#include <cstddef>

// Problem constants
#define BB 4
#define SS 2048
#define EE 1024
#define HH 16
#define DD 64
#define MTOK (BB * SS)     // 8192
#define NQKV (3 * EE)      // 3072
#define SCALE 0.125f
#define NSLICE 16

// GEMM tiling
#define BK 32                          // fp32 K per chunk
#define RSTRIDE 20                     // b32 per smem row (16 b32 data + 4 pad)
#define TILE32 (128 * RSTRIDE)         // 2560 b32 per operand tile
#define A_HI 0
#define A_LO TILE32
#define B_HI (2 * TILE32)
#define B_LO (3 * TILE32)
#define STAGE32 (4 * TILE32)           // 10240 b32 per stage
#define SMEM_BYTES (2 * STAGE32 * 4)   // 81920 B (dynamic)

// ---------------------------------------------------------------------------
// Scratch
// ---------------------------------------------------------------------------
__device__ float g_q[MTOK * EE];
__device__ float g_k[BB * HH][SS][DD];
__device__ float g_v[BB * HH][SS][DD];
__device__ float g_mpart[NSLICE][BB * HH][DD][DD];
__device__ float g_m[BB][HH][DD][DD];
__device__ float g_pt[BB][EE][EE];     // P^T [b][n][k]

// ---------------------------------------------------------------------------
// Helpers
// ---------------------------------------------------------------------------
__device__ __forceinline__ void mma_bf16(float* c, const uint32_t* a, const uint32_t* b) {
    asm volatile(
        "mma.sync.aligned.m16n8k16.row.col.f32.bf16.bf16.f32 "
        "{%0,%1,%2,%3}, {%4,%5,%6,%7}, {%8,%9}, {%0,%1,%2,%3};"
        : "+f"(c[0]), "+f"(c[1]), "+f"(c[2]), "+f"(c[3])
        : "r"(a[0]), "r"(a[1]), "r"(a[2]), "r"(a[3]), "r"(b[0]), "r"(b[1]));
}

// Split float4 into packed bf16 hi pair-regs and lo pair-regs (elem0 in low half).
__device__ __forceinline__ void split4(float4 v, uint32_t& h0, uint32_t& h1,
                                       uint32_t& l0, uint32_t& l1) {
    asm("cvt.rn.bf16x2.f32 %0, %1, %2;" : "=r"(h0) : "f"(v.y), "f"(v.x));
    asm("cvt.rn.bf16x2.f32 %0, %1, %2;" : "=r"(h1) : "f"(v.w), "f"(v.z));
    float hx = __uint_as_float(h0 << 16);
    float hy = __uint_as_float(h0 & 0xFFFF0000u);
    float hz = __uint_as_float(h1 << 16);
    float hw = __uint_as_float(h1 & 0xFFFF0000u);
    asm("cvt.rn.bf16x2.f32 %0, %1, %2;" : "=r"(l0) : "f"(v.y - hy), "f"(v.x - hx));
    asm("cvt.rn.bf16x2.f32 %0, %1, %2;" : "=r"(l1) : "f"(v.w - hw), "f"(v.z - hz));
}

// ---------------------------------------------------------------------------
// bf16x2-split tensor-core GEMM. C tiles 128x128, BK=32, 256 threads, 8 warps
// (warp tile 32x64). A: [m][k] K-contig. B: [n][k] K-contig.
// MODE 0: qkv (scatter epilogue). MODE 1: out (direct epilogue).
// ---------------------------------------------------------------------------
template <int MODE>
__global__ __launch_bounds__(256, 1) void gemm_mma(const float* __restrict__ A,
                                                   const float* __restrict__ Bmat,
                                                   float* __restrict__ Out) {
    extern __shared__ uint32_t sm32[];
    const int tid = threadIdx.x;
    const int wid = tid >> 5, lane = tid & 31;
    const int g = lane >> 2, tg = lane & 3;
    const int warp_m = wid & 3;
    const int warp_n = wid >> 2;
    const int bn = blockIdx.x * 128;
    const int bm = blockIdx.y * 128;

    const float* Ap;
    const float* Bp;
    if (MODE == 0) {
        Ap = A + (size_t)bm * EE;
        Bp = Bmat + (size_t)bn * EE;
    } else {
        const int batch = bm >> 11;
        Ap = &g_q[0] + (size_t)bm * EE;
        Bp = &g_pt[0][0][0] + ((size_t)batch * EE + bn) * EE;
    }

    float acc[2][8][4];
#pragma unroll
    for (int mt = 0; mt < 2; ++mt)
#pragma unroll
        for (int nt = 0; nt < 8; ++nt)
#pragma unroll
            for (int i = 0; i < 4; ++i) acc[mt][nt][i] = 0.0f;

    // Prefetch registers: 4 float4 of A + 4 of B per thread per chunk.
    float4 pa[4], pb[4];
    const int prow = tid >> 3;            // 0..31  (+32 per i)
    const int pc4 = (tid & 7) * 4;        // float col 0..28

    auto ldg_chunk = [&](int k0) {
#pragma unroll
        for (int i = 0; i < 4; ++i) {
            const int row = prow + i * 32;
            pa[i] = *(const float4*)(Ap + (size_t)row * EE + k0 + pc4);
            pb[i] = *(const float4*)(Bp + (size_t)row * EE + k0 + pc4);
        }
    };
    auto sts_chunk = [&](int s) {
        uint32_t* st = sm32 + s * STAGE32;
#pragma unroll
        for (int i = 0; i < 4; ++i) {
            const int row = prow + i * 32;
            const int off = row * RSTRIDE + (pc4 >> 1);   // b32 index
            uint32_t h0, h1, l0, l1;
            split4(pa[i], h0, h1, l0, l1);
            st[A_HI + off] = h0; st[A_HI + off + 1] = h1;
            st[A_LO + off] = l0; st[A_LO + off + 1] = l1;
            split4(pb[i], h0, h1, l0, l1);
            st[B_HI + off] = h0; st[B_HI + off + 1] = h1;
            st[B_LO + off] = l0; st[B_LO + off + 1] = l1;
        }
    };

    ldg_chunk(0);

    const int NK = EE / BK;   // 32
    for (int kc = 0; kc < NK; ++kc) {
        const int s = kc & 1;
        sts_chunk(s);
        __syncthreads();
        if (kc + 1 < NK) ldg_chunk((kc + 1) * BK);

        const uint32_t* st = sm32 + s * STAGE32;
#pragma unroll
        for (int ks = 0; ks < 2; ++ks) {
            const int kb = ks * 8 + tg;
            uint32_t ahi[2][4], alo[2][4];
#pragma unroll
            for (int mt = 0; mt < 2; ++mt) {
                const int r = (warp_m * 32 + mt * 16 + g) * RSTRIDE;
                ahi[mt][0] = st[A_HI + r + kb];
                ahi[mt][1] = st[A_HI + r + 8 * RSTRIDE + kb];
                ahi[mt][2] = st[A_HI + r + kb + 4];
                ahi[mt][3] = st[A_HI + r + 8 * RSTRIDE + kb + 4];
                alo[mt][0] = st[A_LO + r + kb];
                alo[mt][1] = st[A_LO + r + 8 * RSTRIDE + kb];
                alo[mt][2] = st[A_LO + r + kb + 4];
                alo[mt][3] = st[A_LO + r + 8 * RSTRIDE + kb + 4];
            }
            uint32_t bhi[8][2], blo[8][2];
#pragma unroll
            for (int nt = 0; nt < 8; ++nt) {
                const int rn = (warp_n * 64 + nt * 8 + g) * RSTRIDE;
                bhi[nt][0] = st[B_HI + rn + kb];
                bhi[nt][1] = st[B_HI + rn + kb + 4];
                blo[nt][0] = st[B_LO + rn + kb];
                blo[nt][1] = st[B_LO + rn + kb + 4];
            }
#pragma unroll
            for (int mt = 0; mt < 2; ++mt)
#pragma unroll
                for (int nt = 0; nt < 8; ++nt) mma_bf16(acc[mt][nt], ahi[mt], bhi[nt]);
#pragma unroll
            for (int mt = 0; mt < 2; ++mt)
#pragma unroll
                for (int nt = 0; nt < 8; ++nt) mma_bf16(acc[mt][nt], alo[mt], bhi[nt]);
#pragma unroll
            for (int mt = 0; mt < 2; ++mt)
#pragma unroll
                for (int nt = 0; nt < 8; ++nt) mma_bf16(acc[mt][nt], ahi[mt], blo[nt]);
        }
        __syncthreads();
    }

    // Epilogue: direct register -> gmem float2 stores.
#pragma unroll
    for (int mt = 0; mt < 2; ++mt) {
#pragma unroll
        for (int nt = 0; nt < 8; ++nt) {
            const int col = bn + warp_n * 64 + nt * 8 + 2 * tg;
#pragma unroll
            for (int half = 0; half < 2; ++half) {
                const int row = bm + warp_m * 32 + mt * 16 + g + half * 8;
                const float v0 = acc[mt][nt][half * 2 + 0];
                const float v1 = acc[mt][nt][half * 2 + 1];
                if (MODE == 1) {
                    *(float2*)&Out[(size_t)row * EE + col] = make_float2(v0, v1);
                } else {
                    const int h = col / 192;
                    const int jj = col - h * 192;
                    const int bidx = row >> 11;
                    const int sr = row & 2047;
                    if (jj < 64)
                        *(float2*)&g_q[(size_t)row * EE + h * 64 + jj] = make_float2(v0, v1);
                    else if (jj < 128)
                        *(float2*)&g_k[bidx * HH + h][sr][jj - 64] = make_float2(v0, v1);
                    else
                        *(float2*)&g_v[bidx * HH + h][sr][jj - 128] = make_float2(v0, v1);
                }
            }
        }
    }
}

// ---------------------------------------------------------------------------
// kv_reduce partials: grid (64, NSLICE); 64x64 partial K^T V over S/NSLICE rows.
// ---------------------------------------------------------------------------
__global__ __launch_bounds__(256) void kv_reduce() {
    const int bh = blockIdx.x;
    const int sl = blockIdx.y;
    const int tid = threadIdx.x;
    const int tx = tid & 15;
    const int ty = tid >> 4;

    __shared__ float Ks[32][64];
    __shared__ float Vs[32][64];

    float acc[4][4];
#pragma unroll
    for (int i = 0; i < 4; ++i)
#pragma unroll
        for (int j = 0; j < 4; ++j) acc[i][j] = 0.0f;

    const int s_beg = sl * (SS / NSLICE);
    for (int s0 = s_beg; s0 < s_beg + SS / NSLICE; s0 += 32) {
#pragma unroll
        for (int it = 0; it < 2; ++it) {
            const int fid = tid + it * 256;
            const int row = fid >> 4;
            const int c4 = (fid & 15) * 4;
            *(float4*)&Ks[row][c4] = *(const float4*)&g_k[bh][s0 + row][c4];
            *(float4*)&Vs[row][c4] = *(const float4*)&g_v[bh][s0 + row][c4];
        }
        __syncthreads();
#pragma unroll 8
        for (int s = 0; s < 32; ++s) {
            float a[4], b[4];
#pragma unroll
            for (int i = 0; i < 4; ++i) a[i] = Ks[s][ty * 4 + i];
#pragma unroll
            for (int j = 0; j < 4; ++j) b[j] = Vs[s][tx * 4 + j];
#pragma unroll
            for (int i = 0; i < 4; ++i)
#pragma unroll
                for (int j = 0; j < 4; ++j) acc[i][j] += a[i] * b[j];
        }
        __syncthreads();
    }
#pragma unroll
    for (int i = 0; i < 4; ++i)
#pragma unroll
        for (int j = 0; j < 4; ++j)
            g_mpart[sl][bh][ty * 4 + i][tx * 4 + j] = acc[i][j];
}

__global__ __launch_bounds__(256) void merge_m() {
    const int bh = blockIdx.x;
    const int b = bh / HH, h = bh % HH;
    for (int e = threadIdx.x; e < DD * DD; e += 256) {
        float s = 0.0f;
#pragma unroll
        for (int p = 0; p < NSLICE; ++p) s += g_mpart[p][bh][e >> 6][e & 63];
        g_m[b][h][e >> 6][e & 63] = SCALE * s;
    }
}

// ---------------------------------------------------------------------------
// make_p: g_pt[b][c][r] = sum_d M[b][h][rl][d] * w_o[c][h*64+d]  (r = h*64+rl)
// Grid (EE/64, HH). w_o tile resident; M tile streamed per batch.
// Tiles stored TRANSPOSED (d-major) so the d-loop reads rows -> conflict-free.
// Static smem: 2 * 64*68*4 = 34816 B < 48K.
// ---------------------------------------------------------------------------
__global__ __launch_bounds__(256) void make_p(const float* __restrict__ w_o) {
    const int h = blockIdx.y;
    const int c0 = blockIdx.x * 64;
    const int tid = threadIdx.x;
    const int tx = tid & 15;   // rl
    const int ty = tid >> 4;   // c

    __shared__ float Wost[64][68];   // [d][c]
    __shared__ float Mst[64][68];    // [d][rl] (one batch at a time)

    // Load w_o tile transposed: gmem rows are c, cols are d.
#pragma unroll
    for (int it = 0; it < 4; ++it) {
        const int fid = tid + it * 256;
        const int c = fid >> 4;
        const int d4 = (fid & 15) * 4;
        float4 v = *(const float4*)&w_o[(size_t)(c0 + c) * EE + h * 64 + d4];
        Wost[d4 + 0][c] = v.x; Wost[d4 + 1][c] = v.y;
        Wost[d4 + 2][c] = v.z; Wost[d4 + 3][c] = v.w;
    }

    for (int b = 0; b < 4; ++b) {
        __syncthreads();
        // Load M tile transposed: gmem rows are rl, cols are d.
#pragma unroll
        for (int it = 0; it < 4; ++it) {
            const int fid = tid + it * 256;
            const int rl = fid >> 4;
            const int d4 = (fid & 15) * 4;
            float4 v = *(const float4*)&g_m[b][h][rl][d4];
            Mst[d4 + 0][rl] = v.x; Mst[d4 + 1][rl] = v.y;
            Mst[d4 + 2][rl] = v.z; Mst[d4 + 3][rl] = v.w;
        }
        __syncthreads();

        float acc[4][4];
#pragma unroll
        for (int i = 0; i < 4; ++i)
#pragma unroll
            for (int j = 0; j < 4; ++j) acc[i][j] = 0.0f;
#pragma unroll 8
        for (int d = 0; d < 64; ++d) {
            float a[4], bb[4];
#pragma unroll
            for (int i = 0; i < 4; ++i) a[i] = Wost[d][ty * 4 + i];
#pragma unroll
            for (int j = 0; j < 4; ++j) bb[j] = Mst[d][tx * 4 + j];
#pragma unroll
            for (int i = 0; i < 4; ++i)
#pragma unroll
                for (int j = 0; j < 4; ++j) acc[i][j] += a[i] * bb[j];
        }
#pragma unroll
        for (int i = 0; i < 4; ++i) {
            float4 v;
            v.x = acc[i][0]; v.y = acc[i][1]; v.z = acc[i][2]; v.w = acc[i][3];
            *(float4*)&g_pt[b][c0 + ty * 4 + i][h * 64 + tx * 4] = v;
        }
    }
}

// ---------------------------------------------------------------------------
// Launch
// ---------------------------------------------------------------------------
extern "C" void kernel_launch(void* const* d_in, const int* in_sizes, int n_in,
                              void* d_out, int out_size) {
    const float* x = (const float*)d_in[0];
    const float* w_qkv = (const float*)d_in[1];
    const float* w_o = (const float*)d_in[2];
    float* out = (float*)d_out;

    cudaFuncSetAttribute(gemm_mma<0>, cudaFuncAttributeMaxDynamicSharedMemorySize, SMEM_BYTES);
    cudaFuncSetAttribute(gemm_mma<1>, cudaFuncAttributeMaxDynamicSharedMemorySize, SMEM_BYTES);

    gemm_mma<0><<<dim3(NQKV / 128, MTOK / 128), 256, SMEM_BYTES>>>(x, w_qkv, nullptr);
    kv_reduce<<<dim3(BB * HH, NSLICE), 256>>>();
    merge_m<<<BB * HH, 256>>>();
    make_p<<<dim3(EE / 64, HH), 256>>>(w_o);
    gemm_mma<1><<<dim3(EE / 128, MTOK / 128), 256, SMEM_BYTES>>>(nullptr, nullptr, out);
}